// round 9
// baseline (speedup 1.0000x reference)
#include <cuda_runtime.h>

#define NU 100000
#define NP 50000
#define NE 2000000
#define NLAB 500000
#define HD 64

// ---------------- device scratch (addresses resolved via cudaGetSymbolAddress) ----------------
__device__ int g_deg_p[NP];
__device__ int g_deg_u[NU];
__device__ int g_off_p[NP];
__device__ int g_off_u[NU];
__device__ int g_cur_p[NP];
__device__ int g_cur_u[NU];
__device__ __align__(16) int g_csr_src[NE];   // user ids grouped by product (dst)
__device__ __align__(16) int g_csr_dst[NE];   // product ids grouped by user (src)
__device__ __align__(16) float g_tu[NU * HD];
__device__ __align__(16) float g_tp[NP * HD];
__device__ __align__(16) float g_hu[NU * HD];
__device__ __align__(16) float g_hp[NP * HD];
__device__ __align__(16) float g_hu2[NU * HD];
__device__ __align__(16) float g_hp2[NP * HD];
__device__ int g_bsum_p[128];
__device__ int g_bsum_u[128];

// ---------------- init ----------------
__global__ void k_zero_counts(int* __restrict__ deg_u, int* __restrict__ cur_u,
                              int* __restrict__ deg_p, int* __restrict__ cur_p) {
    int i = blockIdx.x * blockDim.x + threadIdx.x;
    if (i < NU) { deg_u[i] = 0; cur_u[i] = 0; }
    if (i < NP) { deg_p[i] = 0; cur_p[i] = 0; }
}

__global__ void k_degree(const int* __restrict__ src, const int* __restrict__ dst,
                         int* __restrict__ deg_p, int* __restrict__ deg_u) {
    int i = blockIdx.x * blockDim.x + threadIdx.x;
    if (i < NE) {
        atomicAdd(&deg_p[dst[i]], 1);
        atomicAdd(&deg_u[src[i]], 1);
    }
}

// ---------------- 3-pass exclusive scan ----------------
__global__ void k_scan1(const int* __restrict__ deg, int n, int* __restrict__ out, int* __restrict__ bsums) {
    __shared__ int s[1024];
    int tid = threadIdx.x;
    int i = blockIdx.x * 1024 + tid;
    int v = (i < n) ? deg[i] : 0;
    s[tid] = v;
    __syncthreads();
    #pragma unroll
    for (int o = 1; o < 1024; o <<= 1) {
        int t = 0;
        if (tid >= o) t = s[tid - o];
        __syncthreads();
        s[tid] += t;
        __syncthreads();
    }
    if (i < n) out[i] = s[tid] - v;   // exclusive
    if (tid == 1023) bsums[blockIdx.x] = s[1023];
}

__global__ void k_scan2(int* __restrict__ bsums, int nb) {
    __shared__ int s[1024];
    int tid = threadIdx.x;
    int v = (tid < nb) ? bsums[tid] : 0;
    s[tid] = v;
    __syncthreads();
    #pragma unroll
    for (int o = 1; o < 1024; o <<= 1) {
        int t = 0;
        if (tid >= o) t = s[tid - o];
        __syncthreads();
        s[tid] += t;
        __syncthreads();
    }
    if (tid < nb) bsums[tid] = s[tid] - v;
}

__global__ void k_scan3(int* __restrict__ out, int n, const int* __restrict__ bsums) {
    int i = blockIdx.x * 1024 + threadIdx.x;
    if (i < n) out[i] += bsums[blockIdx.x];
}

__global__ void k_fill(const int* __restrict__ src, const int* __restrict__ dst,
                       const int* __restrict__ off_p, int* __restrict__ cur_p, int* __restrict__ csr_src,
                       const int* __restrict__ off_u, int* __restrict__ cur_u, int* __restrict__ csr_dst) {
    int i = blockIdx.x * blockDim.x + threadIdx.x;
    if (i < NE) {
        int s = src[i], d = dst[i];
        int p = atomicAdd(&cur_p[d], 1);
        csr_src[off_p[d] + p] = s;
        int q = atomicAdd(&cur_u[s], 1);
        csr_dst[off_u[s] + q] = d;
    }
}

// ---------------- dense node-wise GEMM: out[n,64] = x[n,DIN] @ W[DIN,64] (+b) ----------------
template <int DIN, bool BIAS>
__global__ __launch_bounds__(256) void k_gemm(const float* __restrict__ x,
                                              const float* __restrict__ W,
                                              const float* __restrict__ b,
                                              float* __restrict__ out, int n) {
    __shared__ __align__(16) float Ws[DIN * 64];
    __shared__ __align__(16) float xs[16][DIN];
    int tid = threadIdx.x;
    int row0 = blockIdx.x * 16;

    for (int k = tid; k < DIN * 64; k += 256) Ws[k] = W[k];
    for (int k = tid; k < 16 * DIN; k += 256) {
        int r = k / DIN, c = k % DIN;
        int row = row0 + r;
        xs[r][c] = (row < n) ? x[row * DIN + c] : 0.f;
    }
    __syncthreads();

    int col = tid & 63;
    int rbase = (tid >> 6) * 4;   // 0,4,8,12

    float acc0 = BIAS ? b[col] : 0.f;
    float acc1 = acc0, acc2 = acc0, acc3 = acc0;

    #pragma unroll
    for (int k = 0; k < DIN; k += 4) {
        float w0 = Ws[(k + 0) * 64 + col];
        float w1 = Ws[(k + 1) * 64 + col];
        float w2 = Ws[(k + 2) * 64 + col];
        float w3 = Ws[(k + 3) * 64 + col];
        float4 a0 = *(const float4*)&xs[rbase + 0][k];
        float4 a1 = *(const float4*)&xs[rbase + 1][k];
        float4 a2 = *(const float4*)&xs[rbase + 2][k];
        float4 a3 = *(const float4*)&xs[rbase + 3][k];
        acc0 = fmaf(a0.x, w0, acc0); acc0 = fmaf(a0.y, w1, acc0); acc0 = fmaf(a0.z, w2, acc0); acc0 = fmaf(a0.w, w3, acc0);
        acc1 = fmaf(a1.x, w0, acc1); acc1 = fmaf(a1.y, w1, acc1); acc1 = fmaf(a1.z, w2, acc1); acc1 = fmaf(a1.w, w3, acc1);
        acc2 = fmaf(a2.x, w0, acc2); acc2 = fmaf(a2.y, w1, acc2); acc2 = fmaf(a2.z, w2, acc2); acc2 = fmaf(a2.w, w3, acc2);
        acc3 = fmaf(a3.x, w0, acc3); acc3 = fmaf(a3.y, w1, acc3); acc3 = fmaf(a3.z, w2, acc3); acc3 = fmaf(a3.w, w3, acc3);
    }

    int row = row0 + rbase;
    if (row + 0 < n) out[(row + 0) * 64 + col] = acc0;
    if (row + 1 < n) out[(row + 1) * 64 + col] = acc1;
    if (row + 2 < n) out[(row + 2) * 64 + col] = acc2;
    if (row + 3 < n) out[(row + 3) * 64 + col] = acc3;
}

// ---------------- aggregation: warp per node, CSR gather + mean + add self (+relu) ----------------
template <bool RELU>
__global__ __launch_bounds__(256) void k_agg(const float* __restrict__ t,
                                             const int* __restrict__ csr,
                                             const int* __restrict__ off,
                                             const int* __restrict__ deg,
                                             float* __restrict__ h, int n) {
    int warp = (blockIdx.x * blockDim.x + threadIdx.x) >> 5;
    int lane = threadIdx.x & 31;
    if (warp >= n) return;
    int start = off[warp];
    int d = deg[warp];
    int half = lane >> 4;     // lanes 0-15: even edges, 16-31: odd edges
    int l16 = lane & 15;

    float4 acc = make_float4(0.f, 0.f, 0.f, 0.f);
    for (int e = half; e < d; e += 2) {
        int s = __ldg(&csr[start + e]);
        float4 v = *(const float4*)&t[s * 64 + l16 * 4];
        acc.x += v.x; acc.y += v.y; acc.z += v.z; acc.w += v.w;
    }
    acc.x += __shfl_down_sync(0xffffffffu, acc.x, 16);
    acc.y += __shfl_down_sync(0xffffffffu, acc.y, 16);
    acc.z += __shfl_down_sync(0xffffffffu, acc.z, 16);
    acc.w += __shfl_down_sync(0xffffffffu, acc.w, 16);

    if (lane < 16) {
        float inv = 1.0f / (float)((d > 1) ? d : 1);
        float4 s4 = *(const float4*)&h[warp * 64 + l16 * 4];
        float4 o;
        o.x = fmaf(acc.x, inv, s4.x);
        o.y = fmaf(acc.y, inv, s4.y);
        o.z = fmaf(acc.z, inv, s4.z);
        o.w = fmaf(acc.w, inv, s4.w);
        if (RELU) {
            o.x = fmaxf(o.x, 0.f); o.y = fmaxf(o.y, 0.f);
            o.z = fmaxf(o.z, 0.f); o.w = fmaxf(o.w, 0.f);
        }
        *(float4*)&h[warp * 64 + l16 * 4] = o;
    }
}

// ---------------- classifier: 16 threads per label edge ----------------
__global__ __launch_bounds__(256) void k_classify(const int* __restrict__ lu,
                                                  const int* __restrict__ lp,
                                                  const float* __restrict__ hu2,
                                                  const float* __restrict__ hp2,
                                                  float* __restrict__ out) {
    int gid = blockIdx.x * blockDim.x + threadIdx.x;
    int e = gid >> 4;
    int l = gid & 15;
    if (e >= NLAB) return;
    int u = __ldg(&lu[e]);
    int p = __ldg(&lp[e]);
    float4 a = *(const float4*)&hu2[u * 64 + l * 4];
    float4 b = *(const float4*)&hp2[p * 64 + l * 4];
    float s = a.x * b.x + a.y * b.y + a.z * b.z + a.w * b.w;
    s += __shfl_xor_sync(0xffffffffu, s, 8);
    s += __shfl_xor_sync(0xffffffffu, s, 4);
    s += __shfl_xor_sync(0xffffffffu, s, 2);
    s += __shfl_xor_sync(0xffffffffu, s, 1);
    if (l == 0) out[e] = s;
}

// ---------------- launcher ----------------
extern "C" void kernel_launch(void* const* d_in, const int* in_sizes, int n_in,
                              void* d_out, int out_size) {
    // inputs confirmed (R8 diagnostics): dict order, element counts
    const float* x_user    = (const float*)d_in[0];
    const float* x_product = (const float*)d_in[1];
    const float* W1_buys_l = (const float*)d_in[2];
    const float* b1_buys   = (const float*)d_in[3];
    const float* W1_buys_r = (const float*)d_in[4];
    const float* W1_rev_l  = (const float*)d_in[5];
    const float* b1_rev    = (const float*)d_in[6];
    const float* W1_rev_r  = (const float*)d_in[7];
    const float* W2_buys_l = (const float*)d_in[8];
    const float* b2_buys   = (const float*)d_in[9];
    const float* W2_buys_r = (const float*)d_in[10];
    const float* W2_rev_l  = (const float*)d_in[11];
    const float* b2_rev    = (const float*)d_in[12];
    const float* W2_rev_r  = (const float*)d_in[13];
    const int* edge_src = (const int*)d_in[14];
    const int* edge_dst = (const int*)d_in[15];
    const int* lab_u    = (const int*)d_in[16];
    const int* lab_p    = (const int*)d_in[17];
    float* out = (float*)d_out;

    // REAL device addresses of scratch symbols (root cause of R1-R8: passing the
    // host shadow of a __device__ symbol as a kernel arg silently writes host
    // memory via ATS on GB300). cudaGetSymbolAddress is host-side, capture-safe.
    static int init_done = 0;
    static int *deg_p, *deg_u, *off_p, *off_u, *cur_p, *cur_u;
    static int *csr_src, *csr_dst, *bsum_p, *bsum_u;
    static float *tu, *tp, *hu, *hp, *hu2, *hp2;
    if (!init_done) {
        void* p;
        cudaGetSymbolAddress(&p, g_deg_p); deg_p = (int*)p;
        cudaGetSymbolAddress(&p, g_deg_u); deg_u = (int*)p;
        cudaGetSymbolAddress(&p, g_off_p); off_p = (int*)p;
        cudaGetSymbolAddress(&p, g_off_u); off_u = (int*)p;
        cudaGetSymbolAddress(&p, g_cur_p); cur_p = (int*)p;
        cudaGetSymbolAddress(&p, g_cur_u); cur_u = (int*)p;
        cudaGetSymbolAddress(&p, g_csr_src); csr_src = (int*)p;
        cudaGetSymbolAddress(&p, g_csr_dst); csr_dst = (int*)p;
        cudaGetSymbolAddress(&p, g_bsum_p); bsum_p = (int*)p;
        cudaGetSymbolAddress(&p, g_bsum_u); bsum_u = (int*)p;
        cudaGetSymbolAddress(&p, g_tu); tu = (float*)p;
        cudaGetSymbolAddress(&p, g_tp); tp = (float*)p;
        cudaGetSymbolAddress(&p, g_hu); hu = (float*)p;
        cudaGetSymbolAddress(&p, g_hp); hp = (float*)p;
        cudaGetSymbolAddress(&p, g_hu2); hu2 = (float*)p;
        cudaGetSymbolAddress(&p, g_hp2); hp2 = (float*)p;
        init_done = 1;
    }

    const int nb_p = (NP + 1023) / 1024;   // 49
    const int nb_u = (NU + 1023) / 1024;   // 98

    // ---- build CSR (both directions) ----
    k_zero_counts<<<(NU + 255) / 256, 256>>>(deg_u, cur_u, deg_p, cur_p);
    k_degree<<<(NE + 255) / 256, 256>>>(edge_src, edge_dst, deg_p, deg_u);

    k_scan1<<<nb_p, 1024>>>(deg_p, NP, off_p, bsum_p);
    k_scan2<<<1, 1024>>>(bsum_p, nb_p);
    k_scan3<<<nb_p, 1024>>>(off_p, NP, bsum_p);

    k_scan1<<<nb_u, 1024>>>(deg_u, NU, off_u, bsum_u);
    k_scan2<<<1, 1024>>>(bsum_u, nb_u);
    k_scan3<<<nb_u, 1024>>>(off_u, NU, bsum_u);

    k_fill<<<(NE + 255) / 256, 256>>>(edge_src, edge_dst,
                                      off_p, cur_p, csr_src,
                                      off_u, cur_u, csr_dst);

    // ---- layer 1: transform sources, compute self terms, aggregate ----
    k_gemm<64, false><<<(NU + 15) / 16, 256>>>(x_user, W1_buys_l, nullptr, tu, NU);
    k_gemm<128, false><<<(NP + 15) / 16, 256>>>(x_product, W1_rev_l, nullptr, tp, NP);
    k_gemm<128, true><<<(NP + 15) / 16, 256>>>(x_product, W1_buys_r, b1_buys, hp, NP);
    k_gemm<64, true><<<(NU + 15) / 16, 256>>>(x_user, W1_rev_r, b1_rev, hu, NU);

    k_agg<true><<<(NP * 32 + 255) / 256, 256>>>(tu, csr_src, off_p, deg_p, hp, NP);
    k_agg<true><<<(NU * 32 + 255) / 256, 256>>>(tp, csr_dst, off_u, deg_u, hu, NU);

    // ---- layer 2 ----
    k_gemm<64, false><<<(NU + 15) / 16, 256>>>(hu, W2_buys_l, nullptr, tu, NU);
    k_gemm<64, false><<<(NP + 15) / 16, 256>>>(hp, W2_rev_l, nullptr, tp, NP);
    k_gemm<64, true><<<(NP + 15) / 16, 256>>>(hp, W2_buys_r, b2_buys, hp2, NP);
    k_gemm<64, true><<<(NU + 15) / 16, 256>>>(hu, W2_rev_r, b2_rev, hu2, NU);

    k_agg<false><<<(NP * 32 + 255) / 256, 256>>>(tu, csr_src, off_p, deg_p, hp2, NP);
    k_agg<false><<<(NU * 32 + 255) / 256, 256>>>(tp, csr_dst, off_u, deg_u, hu2, NU);

    // ---- classifier ----
    k_classify<<<(NLAB * 16 + 255) / 256, 256>>>(lab_u, lab_p, hu2, hp2, out);
}

// round 12
// speedup vs baseline: 1.2768x; 1.2768x over previous
#include <cuda_runtime.h>

#define NU 100000
#define NP 50000
#define NE 2000000
#define NLAB 500000
#define HD 64

// ---------------- device scratch ----------------
__device__ int g_deg_p[NP];
__device__ int g_deg_u[NU];
__device__ int g_off_p[NP];
__device__ int g_off_u[NU];
__device__ int g_cur_p[NP];
__device__ int g_cur_u[NU];
__device__ __align__(16) int g_csr_src[NE];
__device__ __align__(16) int g_csr_dst[NE];
__device__ __align__(16) float g_tu[NU * HD];
__device__ __align__(16) float g_tp[NP * HD];
__device__ __align__(16) float g_tu2[NU * HD];
__device__ __align__(16) float g_tp2[NP * HD];
__device__ __align__(16) float g_hu[NU * HD];
__device__ __align__(16) float g_hp[NP * HD];
__device__ __align__(16) float g_hu2[NU * HD];
__device__ __align__(16) float g_hp2[NP * HD];
__device__ int g_bsum_p[128];
__device__ int g_bsum_u[128];

// ---------------- CSR build ----------------
__global__ void k_zero_counts(int* __restrict__ deg_u, int* __restrict__ cur_u,
                              int* __restrict__ deg_p, int* __restrict__ cur_p) {
    int i = blockIdx.x * blockDim.x + threadIdx.x;
    if (i < NU) { deg_u[i] = 0; cur_u[i] = 0; }
    if (i < NP) { deg_p[i] = 0; cur_p[i] = 0; }
}

__global__ void k_degree(const int* __restrict__ src, const int* __restrict__ dst,
                         int* __restrict__ deg_p, int* __restrict__ deg_u) {
    int i = blockIdx.x * blockDim.x + threadIdx.x;
    if (i < NE) {
        atomicAdd(&deg_p[dst[i]], 1);
        atomicAdd(&deg_u[src[i]], 1);
    }
}

__global__ void k_scan1(const int* __restrict__ deg, int n, int* __restrict__ out, int* __restrict__ bsums) {
    __shared__ int s[1024];
    int tid = threadIdx.x;
    int i = blockIdx.x * 1024 + tid;
    int v = (i < n) ? deg[i] : 0;
    s[tid] = v;
    __syncthreads();
    #pragma unroll
    for (int o = 1; o < 1024; o <<= 1) {
        int t = 0;
        if (tid >= o) t = s[tid - o];
        __syncthreads();
        s[tid] += t;
        __syncthreads();
    }
    if (i < n) out[i] = s[tid] - v;
    if (tid == 1023) bsums[blockIdx.x] = s[1023];
}

__global__ void k_scan2(int* __restrict__ bsums, int nb) {
    __shared__ int s[1024];
    int tid = threadIdx.x;
    int v = (tid < nb) ? bsums[tid] : 0;
    s[tid] = v;
    __syncthreads();
    #pragma unroll
    for (int o = 1; o < 1024; o <<= 1) {
        int t = 0;
        if (tid >= o) t = s[tid - o];
        __syncthreads();
        s[tid] += t;
        __syncthreads();
    }
    if (tid < nb) bsums[tid] = s[tid] - v;
}

__global__ void k_scan3(int* __restrict__ out, int n, const int* __restrict__ bsums) {
    int i = blockIdx.x * 1024 + threadIdx.x;
    if (i < n) out[i] += bsums[blockIdx.x];
}

__global__ void k_fill(const int* __restrict__ src, const int* __restrict__ dst,
                       const int* __restrict__ off_p, int* __restrict__ cur_p, int* __restrict__ csr_src,
                       const int* __restrict__ off_u, int* __restrict__ cur_u, int* __restrict__ csr_dst) {
    int i = blockIdx.x * blockDim.x + threadIdx.x;
    if (i < NE) {
        int s = src[i], d = dst[i];
        int p = atomicAdd(&cur_p[d], 1);
        csr_src[off_p[d] + p] = s;
        int q = atomicAdd(&cur_u[s], 1);
        csr_dst[off_u[s] + q] = d;
    }
}

// ---------------- fused dual GEMM: outa = x@Wa, outb = x@Wb + bb  (32 rows/block) ----------------
template <int DIN>
__global__ __launch_bounds__(256) void k_gemm2(const float* __restrict__ x,
                                               const float* __restrict__ Wa,
                                               const float* __restrict__ Wb,
                                               const float* __restrict__ bb,
                                               float* __restrict__ outa,
                                               float* __restrict__ outb, int n) {
    extern __shared__ float sm[];
    float* Was = sm;                  // DIN*64
    float* Wbs = sm + DIN * 64;       // DIN*64
    float* xs  = sm + DIN * 128;      // 32*DIN
    int tid = threadIdx.x;
    int row0 = blockIdx.x * 32;

    for (int i = tid; i < DIN * 64; i += 256) { Was[i] = Wa[i]; Wbs[i] = Wb[i]; }
    for (int i = tid; i < 32 * DIN; i += 256) {
        int r = i / DIN, c = i % DIN;
        int row = row0 + r;
        xs[i] = (row < n) ? x[row * DIN + c] : 0.f;
    }
    __syncthreads();

    int col = tid & 63;
    int g = tid >> 6;                 // 4 row-groups of 8 rows
    const float* xbase = xs + (g * 8) * DIN;

    float bv = bb[col];
    float ta[8], tb[8];
    #pragma unroll
    for (int j = 0; j < 8; j++) { ta[j] = 0.f; tb[j] = bv; }

    #pragma unroll 4
    for (int k = 0; k < DIN; k += 4) {
        float wa0 = Was[(k + 0) * 64 + col];
        float wa1 = Was[(k + 1) * 64 + col];
        float wa2 = Was[(k + 2) * 64 + col];
        float wa3 = Was[(k + 3) * 64 + col];
        float wb0 = Wbs[(k + 0) * 64 + col];
        float wb1 = Wbs[(k + 1) * 64 + col];
        float wb2 = Wbs[(k + 2) * 64 + col];
        float wb3 = Wbs[(k + 3) * 64 + col];
        #pragma unroll
        for (int j = 0; j < 8; j++) {
            float4 xv = *(const float4*)&xbase[j * DIN + k];
            ta[j] = fmaf(xv.x, wa0, ta[j]); ta[j] = fmaf(xv.y, wa1, ta[j]);
            ta[j] = fmaf(xv.z, wa2, ta[j]); ta[j] = fmaf(xv.w, wa3, ta[j]);
            tb[j] = fmaf(xv.x, wb0, tb[j]); tb[j] = fmaf(xv.y, wb1, tb[j]);
            tb[j] = fmaf(xv.z, wb2, tb[j]); tb[j] = fmaf(xv.w, wb3, tb[j]);
        }
    }

    #pragma unroll
    for (int j = 0; j < 8; j++) {
        int row = row0 + g * 8 + j;
        if (row < n) {
            outa[row * 64 + col] = ta[j];
            outb[row * 64 + col] = tb[j];
        }
    }
}

// ---------------- aggregation: warp per node, CSR gather + mean + add self (+relu) ----------------
template <bool RELU>
__global__ __launch_bounds__(256) void k_agg(const float* __restrict__ t,
                                             const int* __restrict__ csr,
                                             const int* __restrict__ off,
                                             const int* __restrict__ deg,
                                             float* __restrict__ h, int n) {
    int warp = (blockIdx.x * blockDim.x + threadIdx.x) >> 5;
    int lane = threadIdx.x & 31;
    if (warp >= n) return;
    int start = off[warp];
    int d = deg[warp];
    int half = lane >> 4;
    int l16 = lane & 15;

    float4 acc = make_float4(0.f, 0.f, 0.f, 0.f);
    for (int e = half; e < d; e += 2) {
        int s = __ldg(&csr[start + e]);
        float4 v = *(const float4*)&t[s * 64 + l16 * 4];
        acc.x += v.x; acc.y += v.y; acc.z += v.z; acc.w += v.w;
    }
    acc.x += __shfl_down_sync(0xffffffffu, acc.x, 16);
    acc.y += __shfl_down_sync(0xffffffffu, acc.y, 16);
    acc.z += __shfl_down_sync(0xffffffffu, acc.z, 16);
    acc.w += __shfl_down_sync(0xffffffffu, acc.w, 16);

    if (lane < 16) {
        float inv = 1.0f / (float)((d > 1) ? d : 1);
        float4 s4 = *(const float4*)&h[warp * 64 + l16 * 4];
        float4 o;
        o.x = fmaf(acc.x, inv, s4.x);
        o.y = fmaf(acc.y, inv, s4.y);
        o.z = fmaf(acc.z, inv, s4.z);
        o.w = fmaf(acc.w, inv, s4.w);
        if (RELU) {
            o.x = fmaxf(o.x, 0.f); o.y = fmaxf(o.y, 0.f);
            o.z = fmaxf(o.z, 0.f); o.w = fmaxf(o.w, 0.f);
        }
        *(float4*)&h[warp * 64 + l16 * 4] = o;
    }
}

// ---------------- classifier: 16 threads per label edge ----------------
__global__ __launch_bounds__(256) void k_classify(const int* __restrict__ lu,
                                                  const int* __restrict__ lp,
                                                  const float* __restrict__ hu2,
                                                  const float* __restrict__ hp2,
                                                  float* __restrict__ out) {
    int gid = blockIdx.x * blockDim.x + threadIdx.x;
    int e = gid >> 4;
    int l = gid & 15;
    if (e >= NLAB) return;
    int u = __ldg(&lu[e]);
    int p = __ldg(&lp[e]);
    float4 a = *(const float4*)&hu2[u * 64 + l * 4];
    float4 b = *(const float4*)&hp2[p * 64 + l * 4];
    float s = a.x * b.x + a.y * b.y + a.z * b.z + a.w * b.w;
    s += __shfl_xor_sync(0xffffffffu, s, 8);
    s += __shfl_xor_sync(0xffffffffu, s, 4);
    s += __shfl_xor_sync(0xffffffffu, s, 2);
    s += __shfl_xor_sync(0xffffffffu, s, 1);
    if (l == 0) out[e] = s;
}

__device__ float g_zero_bias[64];   // zero bias for t-side of fused gemm (a-side unused)

// ---------------- launcher ----------------
extern "C" void kernel_launch(void* const* d_in, const int* in_sizes, int n_in,
                              void* d_out, int out_size) {
    const float* x_user    = (const float*)d_in[0];
    const float* x_product = (const float*)d_in[1];
    const float* W1_buys_l = (const float*)d_in[2];
    const float* b1_buys   = (const float*)d_in[3];
    const float* W1_buys_r = (const float*)d_in[4];
    const float* W1_rev_l  = (const float*)d_in[5];
    const float* b1_rev    = (const float*)d_in[6];
    const float* W1_rev_r  = (const float*)d_in[7];
    const float* W2_buys_l = (const float*)d_in[8];
    const float* b2_buys   = (const float*)d_in[9];
    const float* W2_buys_r = (const float*)d_in[10];
    const float* W2_rev_l  = (const float*)d_in[11];
    const float* b2_rev    = (const float*)d_in[12];
    const float* W2_rev_r  = (const float*)d_in[13];
    const int* edge_src = (const int*)d_in[14];
    const int* edge_dst = (const int*)d_in[15];
    const int* lab_u    = (const int*)d_in[16];
    const int* lab_p    = (const int*)d_in[17];
    float* out = (float*)d_out;

    static int init_done = 0;
    static int *deg_p, *deg_u, *off_p, *off_u, *cur_p, *cur_u;
    static int *csr_src, *csr_dst, *bsum_p, *bsum_u;
    static float *tu, *tp, *tu2, *tp2, *hu, *hp, *hu2, *hp2;
    static cudaStream_t s1;
    static cudaEvent_t ev[8];
    if (!init_done) {
        void* p;
        cudaGetSymbolAddress(&p, g_deg_p); deg_p = (int*)p;
        cudaGetSymbolAddress(&p, g_deg_u); deg_u = (int*)p;
        cudaGetSymbolAddress(&p, g_off_p); off_p = (int*)p;
        cudaGetSymbolAddress(&p, g_off_u); off_u = (int*)p;
        cudaGetSymbolAddress(&p, g_cur_p); cur_p = (int*)p;
        cudaGetSymbolAddress(&p, g_cur_u); cur_u = (int*)p;
        cudaGetSymbolAddress(&p, g_csr_src); csr_src = (int*)p;
        cudaGetSymbolAddress(&p, g_csr_dst); csr_dst = (int*)p;
        cudaGetSymbolAddress(&p, g_bsum_p); bsum_p = (int*)p;
        cudaGetSymbolAddress(&p, g_bsum_u); bsum_u = (int*)p;
        cudaGetSymbolAddress(&p, g_tu);  tu  = (float*)p;
        cudaGetSymbolAddress(&p, g_tp);  tp  = (float*)p;
        cudaGetSymbolAddress(&p, g_tu2); tu2 = (float*)p;
        cudaGetSymbolAddress(&p, g_tp2); tp2 = (float*)p;
        cudaGetSymbolAddress(&p, g_hu);  hu  = (float*)p;
        cudaGetSymbolAddress(&p, g_hp);  hp  = (float*)p;
        cudaGetSymbolAddress(&p, g_hu2); hu2 = (float*)p;
        cudaGetSymbolAddress(&p, g_hp2); hp2 = (float*)p;
        cudaFuncSetAttribute(k_gemm2<64>, cudaFuncAttributeMaxDynamicSharedMemorySize, 40960);
        cudaFuncSetAttribute(k_gemm2<128>, cudaFuncAttributeMaxDynamicSharedMemorySize, 81920);
        cudaStreamCreateWithFlags(&s1, cudaStreamNonBlocking);
        for (int i = 0; i < 8; i++) cudaEventCreateWithFlags(&ev[i], cudaEventDisableTiming);
        init_done = 1;
    }

    const int nb_p = (NP + 1023) / 1024;
    const int nb_u = (NU + 1023) / 1024;
    const int SM64 = 40960, SM128 = 81920;
    cudaStream_t s0 = 0;

    // ---- fork: CSR build on s1, layer-1 GEMMs on s0 ----
    cudaEventRecord(ev[0], s0);
    cudaStreamWaitEvent(s1, ev[0], 0);

    // s1: CSR build chain
    k_zero_counts<<<(NU + 255) / 256, 256, 0, s1>>>(deg_u, cur_u, deg_p, cur_p);
    k_degree<<<(NE + 255) / 256, 256, 0, s1>>>(edge_src, edge_dst, deg_p, deg_u);
    k_scan1<<<nb_p, 1024, 0, s1>>>(deg_p, NP, off_p, bsum_p);
    k_scan2<<<1, 1024, 0, s1>>>(bsum_p, nb_p);
    k_scan3<<<nb_p, 1024, 0, s1>>>(off_p, NP, bsum_p);
    k_scan1<<<nb_u, 1024, 0, s1>>>(deg_u, NU, off_u, bsum_u);
    k_scan2<<<1, 1024, 0, s1>>>(bsum_u, nb_u);
    k_scan3<<<nb_u, 1024, 0, s1>>>(off_u, NU, bsum_u);
    k_fill<<<(NE + 255) / 256, 256, 0, s1>>>(edge_src, edge_dst,
                                             off_p, cur_p, csr_src,
                                             off_u, cur_u, csr_dst);

    // s0: layer-1 fused GEMMs (t = x@Wl, h = x@Wr + b)
    k_gemm2<64><<<(NU + 31) / 32, 256, SM64, s0>>>(x_user, W1_buys_l, W1_rev_r, b1_rev, tu, hu, NU);
    k_gemm2<128><<<(NP + 31) / 32, 256, SM128, s0>>>(x_product, W1_rev_l, W1_buys_r, b1_buys, tp, hp, NP);

    // ---- cross join ----
    cudaEventRecord(ev[1], s0);
    cudaEventRecord(ev[2], s1);
    cudaStreamWaitEvent(s0, ev[2], 0);
    cudaStreamWaitEvent(s1, ev[1], 0);

    // layer-1 aggregation (p-side on s0, u-side on s1)
    k_agg<true><<<(NP * 32 + 255) / 256, 256, 0, s0>>>(tu, csr_src, off_p, deg_p, hp, NP);
    k_agg<true><<<(NU * 32 + 255) / 256, 256, 0, s1>>>(tp, csr_dst, off_u, deg_u, hu, NU);

    // ---- cross join ----
    cudaEventRecord(ev[3], s0);
    cudaEventRecord(ev[4], s1);
    cudaStreamWaitEvent(s0, ev[4], 0);   // s0 needs hu (from s1)
    cudaStreamWaitEvent(s1, ev[3], 0);   // s1 needs hp (from s0)

    // layer-2 fused GEMMs
    k_gemm2<64><<<(NU + 31) / 32, 256, SM64, s0>>>(hu, W2_buys_l, W2_rev_r, b2_rev, tu2, hu2, NU);
    k_gemm2<64><<<(NP + 31) / 32, 256, SM64, s1>>>(hp, W2_rev_l, W2_buys_r, b2_buys, tp2, hp2, NP);

    // ---- cross join ----
    cudaEventRecord(ev[5], s0);
    cudaEventRecord(ev[6], s1);
    cudaStreamWaitEvent(s0, ev[6], 0);   // s0 agg needs hp2 (from s1)
    cudaStreamWaitEvent(s1, ev[5], 0);   // s1 agg needs hu2 (from s0)

    // layer-2 aggregation
    k_agg<false><<<(NP * 32 + 255) / 256, 256, 0, s0>>>(tu2, csr_src, off_p, deg_p, hp2, NP);
    k_agg<false><<<(NU * 32 + 255) / 256, 256, 0, s1>>>(tp2, csr_dst, off_u, deg_u, hu2, NU);

    // ---- join to s0, classify ----
    cudaEventRecord(ev[7], s1);
    cudaStreamWaitEvent(s0, ev[7], 0);
    k_classify<<<(NLAB * 16 + 255) / 256, 256, 0, s0>>>(lab_u, lab_p, hu2, hp2, out);
}

// round 13
// speedup vs baseline: 1.4415x; 1.1290x over previous
#include <cuda_runtime.h>
#include <cuda_fp16.h>

#define NU 100000
#define NP 50000
#define NE 2000000
#define NLAB 500000
#define HD 64

// ---------------- device scratch ----------------
__device__ int g_deg_p[NP];
__device__ int g_deg_u[NU];
__device__ int g_off_p[NP];
__device__ int g_off_u[NU];
__device__ int g_cur_p[NP];
__device__ int g_cur_u[NU];
__device__ __align__(16) int g_csr_src[NE];
__device__ __align__(16) int g_csr_dst[NE];
__device__ __align__(16) __half g_tu[NU * HD];    // fp16 message buffers (gather source)
__device__ __align__(16) __half g_tp[NP * HD];
__device__ __align__(16) __half g_tu2[NU * HD];
__device__ __align__(16) __half g_tp2[NP * HD];
__device__ __align__(16) float g_hu[NU * HD];
__device__ __align__(16) float g_hp[NP * HD];
__device__ __align__(16) float g_hu2[NU * HD];
__device__ __align__(16) float g_hp2[NP * HD];
__device__ int g_bsum_p[128];
__device__ int g_bsum_u[128];

// ---------------- CSR build (per side) ----------------
__global__ void k_zero_side(int* __restrict__ deg, int* __restrict__ cur, int n) {
    int i = blockIdx.x * blockDim.x + threadIdx.x;
    if (i < n) { deg[i] = 0; cur[i] = 0; }
}

__global__ void k_degree_side(const int* __restrict__ key, int* __restrict__ deg) {
    int i = blockIdx.x * blockDim.x + threadIdx.x;
    if (i < NE) atomicAdd(&deg[key[i]], 1);
}

__global__ void k_scan1(const int* __restrict__ deg, int n, int* __restrict__ out, int* __restrict__ bsums) {
    __shared__ int s[1024];
    int tid = threadIdx.x;
    int i = blockIdx.x * 1024 + tid;
    int v = (i < n) ? deg[i] : 0;
    s[tid] = v;
    __syncthreads();
    #pragma unroll
    for (int o = 1; o < 1024; o <<= 1) {
        int t = 0;
        if (tid >= o) t = s[tid - o];
        __syncthreads();
        s[tid] += t;
        __syncthreads();
    }
    if (i < n) out[i] = s[tid] - v;
    if (tid == 1023) bsums[blockIdx.x] = s[1023];
}

__global__ void k_scan2(int* __restrict__ bsums, int nb) {
    __shared__ int s[1024];
    int tid = threadIdx.x;
    int v = (tid < nb) ? bsums[tid] : 0;
    s[tid] = v;
    __syncthreads();
    #pragma unroll
    for (int o = 1; o < 1024; o <<= 1) {
        int t = 0;
        if (tid >= o) t = s[tid - o];
        __syncthreads();
        s[tid] += t;
        __syncthreads();
    }
    if (tid < nb) bsums[tid] = s[tid] - v;
}

__global__ void k_scan3(int* __restrict__ out, int n, const int* __restrict__ bsums) {
    int i = blockIdx.x * 1024 + threadIdx.x;
    if (i < n) out[i] += bsums[blockIdx.x];
}

// group `val` array by `key` array: csr[off[key]+slot] = val
__global__ void k_fill_side(const int* __restrict__ key, const int* __restrict__ val,
                            const int* __restrict__ off, int* __restrict__ cur,
                            int* __restrict__ csr) {
    int i = blockIdx.x * blockDim.x + threadIdx.x;
    if (i < NE) {
        int k = key[i];
        int slot = atomicAdd(&cur[k], 1);
        csr[off[k] + slot] = val[i];
    }
}

// ---------------- fused dual GEMM: outa(half) = x@Wa, outb(f32) = x@Wb + bb ----------------
template <int DIN>
__global__ __launch_bounds__(256) void k_gemm2(const float* __restrict__ x,
                                               const float* __restrict__ Wa,
                                               const float* __restrict__ Wb,
                                               const float* __restrict__ bb,
                                               __half* __restrict__ outa,
                                               float* __restrict__ outb, int n) {
    extern __shared__ float sm[];
    float* Was = sm;
    float* Wbs = sm + DIN * 64;
    float* xs  = sm + DIN * 128;
    int tid = threadIdx.x;
    int row0 = blockIdx.x * 32;

    for (int i = tid; i < DIN * 64; i += 256) { Was[i] = Wa[i]; Wbs[i] = Wb[i]; }
    for (int i = tid; i < 32 * DIN; i += 256) {
        int r = i / DIN, c = i % DIN;
        int row = row0 + r;
        xs[i] = (row < n) ? x[row * DIN + c] : 0.f;
    }
    __syncthreads();

    int col = tid & 63;
    int g = tid >> 6;
    const float* xbase = xs + (g * 8) * DIN;

    float bv = bb[col];
    float ta[8], tb[8];
    #pragma unroll
    for (int j = 0; j < 8; j++) { ta[j] = 0.f; tb[j] = bv; }

    #pragma unroll 4
    for (int k = 0; k < DIN; k += 4) {
        float wa0 = Was[(k + 0) * 64 + col];
        float wa1 = Was[(k + 1) * 64 + col];
        float wa2 = Was[(k + 2) * 64 + col];
        float wa3 = Was[(k + 3) * 64 + col];
        float wb0 = Wbs[(k + 0) * 64 + col];
        float wb1 = Wbs[(k + 1) * 64 + col];
        float wb2 = Wbs[(k + 2) * 64 + col];
        float wb3 = Wbs[(k + 3) * 64 + col];
        #pragma unroll
        for (int j = 0; j < 8; j++) {
            float4 xv = *(const float4*)&xbase[j * DIN + k];
            ta[j] = fmaf(xv.x, wa0, ta[j]); ta[j] = fmaf(xv.y, wa1, ta[j]);
            ta[j] = fmaf(xv.z, wa2, ta[j]); ta[j] = fmaf(xv.w, wa3, ta[j]);
            tb[j] = fmaf(xv.x, wb0, tb[j]); tb[j] = fmaf(xv.y, wb1, tb[j]);
            tb[j] = fmaf(xv.z, wb2, tb[j]); tb[j] = fmaf(xv.w, wb3, tb[j]);
        }
    }

    #pragma unroll
    for (int j = 0; j < 8; j++) {
        int row = row0 + g * 8 + j;
        if (row < n) {
            outa[row * 64 + col] = __float2half_rn(ta[j]);
            outb[row * 64 + col] = tb[j];
        }
    }
}

// ---------------- aggregation: warp per node, fp16 gather + fp32 accumulate ----------------
template <bool RELU>
__global__ __launch_bounds__(256) void k_agg(const __half* __restrict__ t,
                                             const int* __restrict__ csr,
                                             const int* __restrict__ off,
                                             const int* __restrict__ deg,
                                             float* __restrict__ h, int n) {
    int warp = (blockIdx.x * blockDim.x + threadIdx.x) >> 5;
    int lane = threadIdx.x & 31;
    if (warp >= n) return;
    int start = off[warp];
    int d = deg[warp];
    int half = lane >> 4;     // lanes 0-15: even edges, 16-31: odd edges
    int l16 = lane & 15;

    float4 acc = make_float4(0.f, 0.f, 0.f, 0.f);
    for (int e = half; e < d; e += 2) {
        int s = __ldg(&csr[start + e]);
        uint2 r = *(const uint2*)(t + (size_t)s * 64 + l16 * 4);   // 4 halves = 8B/lane, 128B/row
        float2 f0 = __half22float2(*(const __half2*)&r.x);
        float2 f1 = __half22float2(*(const __half2*)&r.y);
        acc.x += f0.x; acc.y += f0.y; acc.z += f1.x; acc.w += f1.y;
    }
    acc.x += __shfl_down_sync(0xffffffffu, acc.x, 16);
    acc.y += __shfl_down_sync(0xffffffffu, acc.y, 16);
    acc.z += __shfl_down_sync(0xffffffffu, acc.z, 16);
    acc.w += __shfl_down_sync(0xffffffffu, acc.w, 16);

    if (lane < 16) {
        float inv = 1.0f / (float)((d > 1) ? d : 1);
        float4 s4 = *(const float4*)&h[warp * 64 + l16 * 4];
        float4 o;
        o.x = fmaf(acc.x, inv, s4.x);
        o.y = fmaf(acc.y, inv, s4.y);
        o.z = fmaf(acc.z, inv, s4.z);
        o.w = fmaf(acc.w, inv, s4.w);
        if (RELU) {
            o.x = fmaxf(o.x, 0.f); o.y = fmaxf(o.y, 0.f);
            o.z = fmaxf(o.z, 0.f); o.w = fmaxf(o.w, 0.f);
        }
        *(float4*)&h[warp * 64 + l16 * 4] = o;
    }
}

// ---------------- classifier: 16 threads per label edge ----------------
__global__ __launch_bounds__(256) void k_classify(const int* __restrict__ lu,
                                                  const int* __restrict__ lp,
                                                  const float* __restrict__ hu2,
                                                  const float* __restrict__ hp2,
                                                  float* __restrict__ out) {
    int gid = blockIdx.x * blockDim.x + threadIdx.x;
    int e = gid >> 4;
    int l = gid & 15;
    if (e >= NLAB) return;
    int u = __ldg(&lu[e]);
    int p = __ldg(&lp[e]);
    float4 a = *(const float4*)&hu2[u * 64 + l * 4];
    float4 b = *(const float4*)&hp2[p * 64 + l * 4];
    float s = a.x * b.x + a.y * b.y + a.z * b.z + a.w * b.w;
    s += __shfl_xor_sync(0xffffffffu, s, 8);
    s += __shfl_xor_sync(0xffffffffu, s, 4);
    s += __shfl_xor_sync(0xffffffffu, s, 2);
    s += __shfl_xor_sync(0xffffffffu, s, 1);
    if (l == 0) out[e] = s;
}

// ---------------- launcher ----------------
extern "C" void kernel_launch(void* const* d_in, const int* in_sizes, int n_in,
                              void* d_out, int out_size) {
    const float* x_user    = (const float*)d_in[0];
    const float* x_product = (const float*)d_in[1];
    const float* W1_buys_l = (const float*)d_in[2];
    const float* b1_buys   = (const float*)d_in[3];
    const float* W1_buys_r = (const float*)d_in[4];
    const float* W1_rev_l  = (const float*)d_in[5];
    const float* b1_rev    = (const float*)d_in[6];
    const float* W1_rev_r  = (const float*)d_in[7];
    const float* W2_buys_l = (const float*)d_in[8];
    const float* b2_buys   = (const float*)d_in[9];
    const float* W2_buys_r = (const float*)d_in[10];
    const float* W2_rev_l  = (const float*)d_in[11];
    const float* b2_rev    = (const float*)d_in[12];
    const float* W2_rev_r  = (const float*)d_in[13];
    const int* edge_src = (const int*)d_in[14];
    const int* edge_dst = (const int*)d_in[15];
    const int* lab_u    = (const int*)d_in[16];
    const int* lab_p    = (const int*)d_in[17];
    float* out = (float*)d_out;

    static int init_done = 0;
    static int *deg_p, *deg_u, *off_p, *off_u, *cur_p, *cur_u;
    static int *csr_src, *csr_dst, *bsum_p, *bsum_u;
    static __half *tu, *tp, *tu2, *tp2;
    static float *hu, *hp, *hu2, *hp2;
    static cudaStream_t s1, s2;
    static cudaEvent_t ev[10];
    if (!init_done) {
        void* p;
        cudaGetSymbolAddress(&p, g_deg_p); deg_p = (int*)p;
        cudaGetSymbolAddress(&p, g_deg_u); deg_u = (int*)p;
        cudaGetSymbolAddress(&p, g_off_p); off_p = (int*)p;
        cudaGetSymbolAddress(&p, g_off_u); off_u = (int*)p;
        cudaGetSymbolAddress(&p, g_cur_p); cur_p = (int*)p;
        cudaGetSymbolAddress(&p, g_cur_u); cur_u = (int*)p;
        cudaGetSymbolAddress(&p, g_csr_src); csr_src = (int*)p;
        cudaGetSymbolAddress(&p, g_csr_dst); csr_dst = (int*)p;
        cudaGetSymbolAddress(&p, g_bsum_p); bsum_p = (int*)p;
        cudaGetSymbolAddress(&p, g_bsum_u); bsum_u = (int*)p;
        cudaGetSymbolAddress(&p, g_tu);  tu  = (__half*)p;
        cudaGetSymbolAddress(&p, g_tp);  tp  = (__half*)p;
        cudaGetSymbolAddress(&p, g_tu2); tu2 = (__half*)p;
        cudaGetSymbolAddress(&p, g_tp2); tp2 = (__half*)p;
        cudaGetSymbolAddress(&p, g_hu);  hu  = (float*)p;
        cudaGetSymbolAddress(&p, g_hp);  hp  = (float*)p;
        cudaGetSymbolAddress(&p, g_hu2); hu2 = (float*)p;
        cudaGetSymbolAddress(&p, g_hp2); hp2 = (float*)p;
        cudaFuncSetAttribute(k_gemm2<64>, cudaFuncAttributeMaxDynamicSharedMemorySize, 40960);
        cudaFuncSetAttribute(k_gemm2<128>, cudaFuncAttributeMaxDynamicSharedMemorySize, 81920);
        cudaStreamCreateWithFlags(&s1, cudaStreamNonBlocking);
        cudaStreamCreateWithFlags(&s2, cudaStreamNonBlocking);
        for (int i = 0; i < 10; i++) cudaEventCreateWithFlags(&ev[i], cudaEventDisableTiming);
        init_done = 1;
    }

    const int nb_p = (NP + 1023) / 1024;
    const int nb_u = (NU + 1023) / 1024;
    const int SM64 = 40960, SM128 = 81920;
    cudaStream_t s0 = 0;

    // ---- fork ----
    cudaEventRecord(ev[0], s0);
    cudaStreamWaitEvent(s1, ev[0], 0);
    cudaStreamWaitEvent(s2, ev[0], 0);

    // s1: p-side CSR (group user ids by product)
    k_zero_side<<<(NP + 255) / 256, 256, 0, s1>>>(deg_p, cur_p, NP);
    k_degree_side<<<(NE + 255) / 256, 256, 0, s1>>>(edge_dst, deg_p);
    k_scan1<<<nb_p, 1024, 0, s1>>>(deg_p, NP, off_p, bsum_p);
    k_scan2<<<1, 1024, 0, s1>>>(bsum_p, nb_p);
    k_scan3<<<nb_p, 1024, 0, s1>>>(off_p, NP, bsum_p);
    k_fill_side<<<(NE + 255) / 256, 256, 0, s1>>>(edge_dst, edge_src, off_p, cur_p, csr_src);

    // s2: u-side CSR (group product ids by user)
    k_zero_side<<<(NU + 255) / 256, 256, 0, s2>>>(deg_u, cur_u, NU);
    k_degree_side<<<(NE + 255) / 256, 256, 0, s2>>>(edge_src, deg_u);
    k_scan1<<<nb_u, 1024, 0, s2>>>(deg_u, NU, off_u, bsum_u);
    k_scan2<<<1, 1024, 0, s2>>>(bsum_u, nb_u);
    k_scan3<<<nb_u, 1024, 0, s2>>>(off_u, NU, bsum_u);
    k_fill_side<<<(NE + 255) / 256, 256, 0, s2>>>(edge_src, edge_dst, off_u, cur_u, csr_dst);

    // s0: layer-1 fused GEMMs
    k_gemm2<64><<<(NU + 31) / 32, 256, SM64, s0>>>(x_user, W1_buys_l, W1_rev_r, b1_rev, tu, hu, NU);
    k_gemm2<128><<<(NP + 31) / 32, 256, SM128, s0>>>(x_product, W1_rev_l, W1_buys_r, b1_buys, tp, hp, NP);
    cudaEventRecord(ev[1], s0);

    // layer-1 aggregation: p-agg on s1 (needs csr_p + tu + hp), u-agg on s2
    cudaStreamWaitEvent(s1, ev[1], 0);
    cudaStreamWaitEvent(s2, ev[1], 0);
    k_agg<true><<<(NP * 32 + 255) / 256, 256, 0, s1>>>(tu, csr_src, off_p, deg_p, hp, NP);
    k_agg<true><<<(NU * 32 + 255) / 256, 256, 0, s2>>>(tp, csr_dst, off_u, deg_u, hu, NU);

    // layer-2 GEMMs: u-gemm on s2 (reads hu), p-gemm on s1 (reads hp)
    k_gemm2<64><<<(NP + 31) / 32, 256, SM64, s1>>>(hp, W2_rev_l, W2_buys_r, b2_buys, tp2, hp2, NP);
    k_gemm2<64><<<(NU + 31) / 32, 256, SM64, s2>>>(hu, W2_buys_l, W2_rev_r, b2_rev, tu2, hu2, NU);
    cudaEventRecord(ev[2], s1);   // hp2, tp2 ready
    cudaEventRecord(ev[3], s2);   // hu2, tu2 ready

    // layer-2 aggregation: p-agg2 on s1 needs tu2 (s2); u-agg2 on s2 needs tp2 (s1)
    cudaStreamWaitEvent(s1, ev[3], 0);
    cudaStreamWaitEvent(s2, ev[2], 0);
    k_agg<false><<<(NP * 32 + 255) / 256, 256, 0, s1>>>(tu2, csr_src, off_p, deg_p, hp2, NP);
    k_agg<false><<<(NU * 32 + 255) / 256, 256, 0, s2>>>(tp2, csr_dst, off_u, deg_u, hu2, NU);

    // ---- join, classify ----
    cudaEventRecord(ev[4], s1);
    cudaEventRecord(ev[5], s2);
    cudaStreamWaitEvent(s0, ev[4], 0);
    cudaStreamWaitEvent(s0, ev[5], 0);
    k_classify<<<(NLAB * 16 + 255) / 256, 256, 0, s0>>>(lab_u, lab_p, hu2, hp2, out);
}